// round 15
// baseline (speedup 1.0000x reference)
#include <cuda_runtime.h>
#include <cuda_fp16.h>
#include <cstdint>

// Conv as implicit GEMM, single-pass fp16 (fp32 acc), tap-decomposed K.
// K order: k = (r*3+s)*128 + c. BK=64 = half a tap -> 18 chunks.
// CTA 128(oc) x 128(pix), 128 threads = 4 warps (2Mx2N), warp tile 64x64
// (128 B LDSM per MMA vs 192 at 64x32 -> L1 under the 128 B/cyc cap).
// 2-stage cp.async ring, 2 CTAs/SM.

#define C_IN   128
#define HWI    3136
#define NPIX   100352
#define KDIM   1152
#define BK     64
#define NCHUNK 18
#define PITCH  144        // smem row pitch bytes (128B data + 16 pad)

#define OFF_A   0
#define OFF_B   18432     // 128*144
#define STAGE_B 36864
#define NSTAGE  2
#define SMEM_TOTAL (NSTAGE * STAGE_B)   // 73728

__device__ __align__(16) __half g_wh[256 * KDIM];                 // [oc][tap*128+c]
__device__ __align__(16) __half g_xh[(size_t)32 * HWI * C_IN];    // NHWC fp16, 51MB

static __device__ __forceinline__ uint32_t s2u(const void* p) {
    uint32_t a;
    asm("{ .reg .u64 t; cvta.to.shared.u64 t, %1; cvt.u32.u64 %0, t; }" : "=r"(a) : "l"(p));
    return a;
}

static __device__ __forceinline__ void cp16(uint32_t dst, const void* src) {
    asm volatile("cp.async.cg.shared.global [%0], [%1], 16;" :: "r"(dst), "l"(src));
}

static __device__ __forceinline__ void cp16z(uint32_t dst, const void* src, uint32_t src_sz) {
    asm volatile("cp.async.cg.shared.global [%0], [%1], 16, %2;"
                 :: "r"(dst), "l"(src), "r"(src_sz));
}

static __device__ __forceinline__ void ldsm4(uint32_t* r, uint32_t addr) {
    asm volatile("ldmatrix.sync.aligned.m8n8.x4.shared.b16 {%0,%1,%2,%3}, [%4];"
                 : "=r"(r[0]), "=r"(r[1]), "=r"(r[2]), "=r"(r[3]) : "r"(addr));
}

static __device__ __forceinline__ void mma16816(float* c, const uint32_t* a,
                                                uint32_t b0, uint32_t b1) {
    asm volatile(
        "mma.sync.aligned.m16n8k16.row.col.f32.f16.f16.f32 "
        "{%0,%1,%2,%3}, {%4,%5,%6,%7}, {%8,%9}, {%0,%1,%2,%3};"
        : "+f"(c[0]), "+f"(c[1]), "+f"(c[2]), "+f"(c[3])
        : "r"(a[0]), "r"(a[1]), "r"(a[2]), "r"(a[3]), "r"(b0), "r"(b1));
}

// ---------- pre-kernel 1: weights fp32 -> fp16, reordered to k=(tap)*128+c ----------
__global__ void prep_w(const float* __restrict__ w) {
    const int gid = blockIdx.x * 256 + threadIdx.x;   // 36864 = 256 oc x 144 segs
    const int oc = gid / 144;
    const int j  = gid - oc * 144;
    const int tap = j >> 4;
    const int c0  = (j & 15) * 8;
    __half h[8];
    #pragma unroll
    for (int e = 0; e < 8; ++e)
        h[e] = __float2half_rn(w[oc * KDIM + (c0 + e) * 9 + tap]);
    *(uint4*)&g_wh[oc * KDIM + j * 8] = *(uint4*)h;
}

// ---------- pre-kernel 2: x fp32 NCHW -> fp16 NHWC (smem transpose) ----------
__global__ void prep_nhwc(const float* __restrict__ x) {
    __shared__ __half sm[64][136];                    // 272B pitch: 16B-aligned reads
    const int hw0 = blockIdx.x * 64;
    const int n   = blockIdx.y;
    const int tid = threadIdx.x;
    const int c4  = tid >> 6;
    const int hwi = tid & 63;
    const float* __restrict__ xn = x + (size_t)n * C_IN * HWI;
    #pragma unroll
    for (int cc = 0; cc < 32; ++cc) {
        const int c = c4 * 32 + cc;
        sm[hwi][c] = __float2half_rn(xn[(size_t)c * HWI + hw0 + hwi]);
    }
    __syncthreads();
    const int row  = tid >> 2;
    const int part = tid & 3;
    __half* dst = &g_xh[((size_t)(n * HWI + hw0 + row)) * C_IN + part * 32];
    const __half* srcp = &sm[row][part * 32];
    #pragma unroll
    for (int q = 0; q < 4; ++q)
        *(uint4*)(dst + q * 8) = *(const uint4*)(srcp + q * 8);
}

// ---------- main GEMM kernel ----------
__global__ __launch_bounds__(128, 2)
void conv_main(const float* __restrict__ bias, float* __restrict__ out)
{
    extern __shared__ __align__(16) char smem[];
    const uint32_t sb = s2u(smem);

    const int tid  = threadIdx.x;
    const int lane = tid & 31;
    const int wid  = tid >> 5;
    const int oc0  = blockIdx.x * 128;
    const int pix0 = blockIdx.y * 128;

    const int wm = wid & 1;       // M: 2 x 64
    const int wn = wid >> 1;      // N: 2 x 64

    // ---- fill chores: A 1024 x 16B, B 1024 x 16B -> 8 each per thread ----
    // chore i: row = (tid>>3) + 16*i, seg = tid&7
    const int rowA = tid >> 3;
    const int segA = tid & 7;
    const uint32_t dDst0 = (uint32_t)(rowA * PITCH + segA * 16);
    const char* aSrc0 = (const char*)g_wh + ((size_t)(oc0 + rowA) * KDIM + segA * 8) * 2;

    const char* bBase[8];
    int bOh[8], bOw[8];
    #pragma unroll
    for (int i = 0; i < 8; ++i) {
        const int row = rowA + 16 * i;       // 0..127
        const int pg = pix0 + row;
        const int n  = pg / HWI;
        const int hw = pg - n * HWI;
        bOh[i] = hw / 56;
        bOw[i] = hw - bOh[i] * 56;
        bBase[i] = (const char*)g_xh + ((size_t)n * HWI * C_IN + segA * 8) * 2;
    }

    // ---- ldmatrix lane addressing ----
    const uint32_t aOffB = (uint32_t)((wm * 64 + (lane & 15)) * PITCH + (lane >> 4) * 16);
    const int bRow = ((lane >> 4) << 3) | (lane & 7);
    const int bSel = (lane >> 3) & 1;
    const uint32_t bOffB = (uint32_t)((wn * 64 + bRow) * PITCH + bSel * 16);

    float acc[4][8][4];
    #pragma unroll
    for (int i = 0; i < 4; i++)
        #pragma unroll
        for (int j = 0; j < 8; j++)
            #pragma unroll
            for (int q = 0; q < 4; q++)
                acc[i][j][q] = 0.0f;

    // ---- fill one stage with chunk ck (BK=64 = half tap) ----
    auto fill_stage = [&](int ck, uint32_t st) {
        const int tp  = ck >> 1;
        const int fr  = (tp * 11) >> 5;           // tp/3 for tp<9
        const int fs  = tp - fr * 3;
        const int fc0 = (ck & 1) * 64;
        const uint64_t kB = (uint64_t)ck * BK * 2;
        #pragma unroll
        for (int i = 0; i < 8; ++i)
            cp16(st + OFF_A + dDst0 + (uint32_t)(i * 16 * PITCH),
                 aSrc0 + kB + (size_t)i * 16 * KDIM * 2);
        #pragma unroll
        for (int i = 0; i < 8; ++i) {
            const int ih = bOh[i] + fr - 1;
            const int iw = bOw[i] + fs - 1;
            const uint32_t ok = ((unsigned)ih < 56u && (unsigned)iw < 56u) ? 16u : 0u;
            const char* src = bBase[i] + ((ptrdiff_t)(ih * 56 + iw) * C_IN + fc0) * 2;
            cp16z(st + OFF_B + dDst0 + (uint32_t)(i * 16 * PITCH), src, ok);
        }
        asm volatile("cp.async.commit_group;" ::: "memory");
    };

    // ---- prologue: fill stage 0 with chunk 0 ----
    fill_stage(0, sb);

    #pragma unroll 1
    for (int chunk = 0; chunk < NCHUNK; ++chunk) {
        asm volatile("cp.async.wait_group 0;" ::: "memory");
        __syncthreads();

        // ---- issue chunk+1 into the other stage ----
        if (chunk + 1 < NCHUNK)
            fill_stage(chunk + 1, sb + (uint32_t)(((chunk + 1) & 1) * STAGE_B));

        // ---- MMA from stage chunk%2: 4 k16 steps x (4M x 8N tiles) ----
        const uint32_t bufS = sb + (uint32_t)((chunk & 1) * STAGE_B);
        #pragma unroll
        for (int ks = 0; ks < 4; ++ks) {
            const uint32_t ko = (uint32_t)(ks * 32);
            uint32_t bf[16];
            #pragma unroll
            for (int nb = 0; nb < 4; ++nb)
                ldsm4(&bf[nb * 4], bufS + OFF_B + bOffB + ko + (uint32_t)(nb * 16 * PITCH));
            uint32_t af[16];
            #pragma unroll
            for (int mt = 0; mt < 4; ++mt)
                ldsm4(&af[mt * 4], bufS + OFF_A + aOffB + ko + (uint32_t)(mt * 16 * PITCH));
            #pragma unroll
            for (int mt = 0; mt < 4; ++mt)
                #pragma unroll
                for (int nt = 0; nt < 8; ++nt)
                    mma16816(acc[mt][nt], &af[mt * 4], bf[nt * 2], bf[nt * 2 + 1]);
        }
    }

    // ---- epilogue ----
    #pragma unroll
    for (int mt = 0; mt < 4; ++mt) {
        const int r0 = oc0 + wm * 64 + mt * 16 + (lane >> 2);
        const int r1 = r0 + 8;
        const float bv0 = __ldg(&bias[r0]);
        const float bv1 = __ldg(&bias[r1]);
        #pragma unroll
        for (int nt = 0; nt < 8; ++nt) {
            const int pg   = pix0 + wn * 64 + nt * 8 + (lane & 3) * 2;
            const int nimg = pg / HWI;
            const int hw   = pg - nimg * HWI;
            const float* c = acc[mt][nt];
            float2 v0 = make_float2(c[0] + bv0, c[1] + bv0);
            float2 v1 = make_float2(c[2] + bv1, c[3] + bv1);
            *(float2*)&out[((size_t)nimg * 256 + r0) * HWI + hw] = v0;
            *(float2*)&out[((size_t)nimg * 256 + r1) * HWI + hw] = v1;
        }
    }
}

extern "C" void kernel_launch(void* const* d_in, const int* in_sizes, int n_in,
                              void* d_out, int out_size)
{
    const float* x    = (const float*)d_in[0];   // [32,128,56,56]
    const float* wgt  = (const float*)d_in[1];   // [256,128,3,3]
    const float* bias = (const float*)d_in[2];   // [256]
    float* out        = (float*)d_out;           // [32,256,56,56]

    cudaFuncSetAttribute(conv_main,
                         cudaFuncAttributeMaxDynamicSharedMemorySize, SMEM_TOTAL);

    prep_w<<<144, 256>>>(wgt);
    prep_nhwc<<<dim3(HWI / 64, 32), 256>>>(x);
    dim3 grid(2, NPIX / 128);                    // oc fast -> L2 reuse of B
    conv_main<<<grid, 128, SMEM_TOTAL>>>(bias, out);
}